// round 8
// baseline (speedup 1.0000x reference)
#include <cuda_runtime.h>
#include <cuda_fp16.h>
#include <cuda_bf16.h>
#include <stdint.h>

// Problem constants
#define OUTF   11008
#define INF    4096
#define MTOT   512
#define NUM_GROUPS 1409024               // OUTF*INF/32

#define N_TILE 128
#define M_TILE 128
#define KCHUNK 64
#define NCHUNK (INF / KCHUNK)   // 64
#define NTHREADS 256

#define PITCH 144                        // 128B data + 16B pad per row (conflict-free ldmatrix)
#define STAGE_BYTES (128 * PITCH)        // 18432 per tile (A or B)
#define SMEM_BYTES (1024 + 4 * STAGE_BYTES)  // bias header + 2 stages x (A+B) = 74752

// element counts for input identification (all distinct)
#define N_X   (MTOT * INF)               // 2,097,152 fp32
#define N_WQ  (NUM_GROUPS * 12)          // 16,908,288 int32
#define N_WN  NUM_GROUPS                 // 1,409,024 fp16 (dtype uncertain!)
#define N_B   OUTF                       // 11,008 fp32

__device__ __align__(16) __half g_xh[MTOT * INF];   // fp16-converted activations (4 MB)
__device__ __align__(16) __half g_wn[NUM_GROUPS];   // normalized norms (2.8 MB)
__device__ int g_wn_mode;

// ---------------- helpers ----------------
__device__ __forceinline__ uint32_t smem_u32(const void* p) {
    uint32_t a;
    asm("{ .reg .u64 t; cvta.to.shared.u64 t, %1; cvt.u32.u64 %0, t; }" : "=r"(a) : "l"(p));
    return a;
}

__device__ __forceinline__ void sts128(uint32_t addr, uint4 v) {
    asm volatile("st.shared.v4.b32 [%0], {%1,%2,%3,%4};"
                 :: "r"(addr), "r"(v.x), "r"(v.y), "r"(v.z), "r"(v.w) : "memory");
}

__device__ __forceinline__ void cpasync16(uint32_t dst, const void* src) {
    asm volatile("cp.async.cg.shared.global [%0], [%1], 16;" :: "r"(dst), "l"(src) : "memory");
}

__device__ __forceinline__ void ldm_x4(uint32_t* r, uint32_t addr) {
    asm volatile("ldmatrix.sync.aligned.m8n8.x4.shared.b16 {%0,%1,%2,%3}, [%4];"
                 : "=r"(r[0]), "=r"(r[1]), "=r"(r[2]), "=r"(r[3]) : "r"(addr));
}

__device__ __forceinline__ void mma16816(float* c, const uint32_t* a, const uint32_t b0, const uint32_t b1) {
    asm volatile(
        "mma.sync.aligned.m16n8k16.row.col.f32.f16.f16.f32 "
        "{%0,%1,%2,%3}, {%4,%5,%6,%7}, {%8,%9}, {%0,%1,%2,%3};"
        : "+f"(c[0]), "+f"(c[1]), "+f"(c[2]), "+f"(c[3])
        : "r"(a[0]), "r"(a[1]), "r"(a[2]), "r"(a[3]), "r"(b0), "r"(b1));
}

// Decode 8 3-bit codes from 3 bytes (each held in an int32), dequantize, pack to 4x half2.
__device__ __forceinline__ uint4 dec8(int b0, int b1, int b2, float a, float nb) {
    float w0 = fmaf((float)(b0 & 7), a, nb);
    float w1 = fmaf((float)((b0 >> 3) & 7), a, nb);
    float w2 = fmaf((float)(((b0 >> 6) & 3) | ((b1 & 1) << 2)), a, nb);
    float w3 = fmaf((float)((b1 >> 1) & 7), a, nb);
    float w4 = fmaf((float)((b1 >> 4) & 7), a, nb);
    float w5 = fmaf((float)(((b1 >> 7) & 1) | ((b2 & 3) << 1)), a, nb);
    float w6 = fmaf((float)((b2 >> 2) & 7), a, nb);
    float w7 = fmaf((float)((b2 >> 5) & 7), a, nb);
    uint4 u;
    asm("cvt.rn.f16x2.f32 %0, %1, %2;" : "=r"(u.x) : "f"(w1), "f"(w0));
    asm("cvt.rn.f16x2.f32 %0, %1, %2;" : "=r"(u.y) : "f"(w3), "f"(w2));
    asm("cvt.rn.f16x2.f32 %0, %1, %2;" : "=r"(u.z) : "f"(w5), "f"(w4));
    asm("cvt.rn.f16x2.f32 %0, %1, %2;" : "=r"(u.w) : "f"(w7), "f"(w6));
    return u;
}

// ---------------- weight_norm dtype detection + normalization ----------------
// Norms are known to lie in (0.01, 0.11). Vote over first 256 elements under
// each candidate interpretation; pick the interpretation with the most
// in-range values. Separations: true f32 -> (256, ~0, ~128); true f16 ->
// (~0, 256, ~0); true bf16 -> (~0, ~0, 256).
__global__ void detect_wn_kernel(const void* __restrict__ wn) {
    int vf32 = 0, vf16 = 0, vbf = 0;
    for (int i = 0; i < 256; i++) {
        float a = ((const float*)wn)[i];
        if (a > 0.009f && a < 0.115f) vf32++;
        float b = __half2float(((const __half*)wn)[i]);
        if (b > 0.009f && b < 0.115f) vf16++;
        float c = __bfloat162float(((const __nv_bfloat16*)wn)[i]);
        if (c > 0.009f && c < 0.115f) vbf++;
    }
    int mode = 1;                       // default: fp16 as declared
    int best = vf16;
    if (vf32 > best) { best = vf32; mode = 0; }
    if (vbf  > best) { best = vbf;  mode = 2; }
    g_wn_mode = mode;
}

__global__ void __launch_bounds__(512) convert_wn_kernel(const void* __restrict__ wn) {
    int i = blockIdx.x * blockDim.x + threadIdx.x;
    if (i >= NUM_GROUPS) return;
    int mode = g_wn_mode;
    float v;
    if (mode == 0)      v = ((const float*)wn)[i];
    else if (mode == 1) v = __half2float(((const __half*)wn)[i]);
    else                v = __bfloat162float(((const __nv_bfloat16*)wn)[i]);
    g_wn[i] = __float2half_rn(v);
}

// ---------------- x fp32 -> fp16 conversion ----------------
__global__ void __launch_bounds__(512) convert_x_kernel(const float* __restrict__ x) {
    int i = blockIdx.x * blockDim.x + threadIdx.x;   // one half2 per thread
    float2 v = ((const float2*)x)[i];
    ((__half2*)g_xh)[i] = __floats2half2_rn(v.x, v.y);
}

// ---------------- fused dequant + GEMM (HMMA; tcgen05 unavailable on base sm_103 target) ----
__global__ void __launch_bounds__(NTHREADS) l3b_gemm(
    const int* __restrict__ wq,
    const float* __restrict__ bias, float* __restrict__ out)
{
    extern __shared__ char smem[];
    const uint32_t sb = smem_u32(smem);
    const int tid = threadIdx.x;
    const int wid = tid >> 5, lid = tid & 31;
    const int wm = wid >> 2, wn_ = wid & 3;          // 2x4 warp grid
    const int m0 = blockIdx.x * M_TILE;              // m fast-varying: 4 CTAs share weights in L2
    const int n0 = blockIdx.y * N_TILE;

    float* bias_s = (float*)(smem);
    const uint32_t As0 = sb + 1024;
    const uint32_t Bs0 = As0 + 2 * STAGE_BYTES;

    if (tid < N_TILE) bias_s[tid] = bias[n0 + tid];

    // dequant task: thread -> (row r in 0..127, half-chunk sub in 0..1); one 32-group each
    const int r = tid >> 1, sub = tid & 1;
    const long grow = (long)(n0 + r) * (INF / 32);
    const uint32_t brow_off = (uint32_t)(r * PITCH + sub * 64);

    // ldmatrix lane addressing
    const uint32_t a_lrow = (uint32_t)(lid & 15);
    const uint32_t a_lkoff = (uint32_t)((lid >> 4) * 8);
    const uint32_t b_lrow = (uint32_t)(((lid >> 4) << 3) + (lid & 7));
    const uint32_t b_lkoff = (uint32_t)(((lid >> 3) & 1) * 8);

    float acc[4][4][4];
    #pragma unroll
    for (int mt = 0; mt < 4; mt++)
        #pragma unroll
        for (int nt = 0; nt < 4; nt++)
            #pragma unroll
            for (int e = 0; e < 4; e++) acc[mt][nt][e] = 0.0f;

    // ---- prologue: stage chunk 0 into buffer 0 ----
    {
        #pragma unroll
        for (int p = 0; p < 4; p++) {
            int idx = p * NTHREADS + tid;                 // 0..1023
            int row = idx >> 3, col = idx & 7;
            cpasync16(As0 + (uint32_t)(row * PITCH + col * 16),
                      g_xh + (size_t)(m0 + row) * INF + col * 8);
        }
        asm volatile("cp.async.commit_group;" ::: "memory");
        const long g = grow + sub;
        const int4* pk = (const int4*)wq + g * 3;
        int4 w0 = __ldg(pk), w1 = __ldg(pk + 1), w2 = __ldg(pk + 2);
        float norm = __half2float(g_wn[g]);
        float aa = norm * (2.0f / 7.0f), nb = -norm;
        sts128(Bs0 + brow_off +  0, dec8(w0.x, w0.y, w0.z, aa, nb));
        sts128(Bs0 + brow_off + 16, dec8(w0.w, w1.x, w1.y, aa, nb));
        sts128(Bs0 + brow_off + 32, dec8(w1.z, w1.w, w2.x, aa, nb));
        sts128(Bs0 + brow_off + 48, dec8(w2.y, w2.z, w2.w, aa, nb));
        asm volatile("cp.async.wait_group 0;" ::: "memory");
        __syncthreads();
    }

    #pragma unroll 1
    for (int i = 0; i < NCHUNK; i++) {
        const int s = i & 1;
        const uint32_t As = As0 + s * STAGE_BYTES;
        const uint32_t Bs = Bs0 + s * STAGE_BYTES;
        const uint32_t Asn = As0 + (s ^ 1) * STAGE_BYTES;
        const uint32_t Bsn = Bs0 + (s ^ 1) * STAGE_BYTES;

        int4 w0, w1, w2; float aa = 0.f, nb = 0.f;
        const bool more = (i + 1 < NCHUNK);
        if (more) {
            #pragma unroll
            for (int p = 0; p < 4; p++) {
                int idx = p * NTHREADS + tid;
                int row = idx >> 3, col = idx & 7;
                cpasync16(Asn + (uint32_t)(row * PITCH + col * 16),
                          g_xh + (size_t)(m0 + row) * INF + (i + 1) * KCHUNK + col * 8);
            }
            asm volatile("cp.async.commit_group;" ::: "memory");
            const long g = grow + (i + 1) * 2 + sub;
            const int4* pk = (const int4*)wq + g * 3;
            w0 = __ldg(pk); w1 = __ldg(pk + 1); w2 = __ldg(pk + 2);
            float norm = __half2float(g_wn[g]);
            aa = norm * (2.0f / 7.0f); nb = -norm;
        }

        // ---- compute chunk i: 4 k16 steps ----
        #pragma unroll
        for (int ks = 0; ks < 4; ks++) {
            uint32_t af[4][4], bf[2][4];
            #pragma unroll
            for (int mt = 0; mt < 4; mt++) {
                uint32_t addr = As + (uint32_t)((wm * 64 + mt * 16 + a_lrow) * PITCH)
                              + (uint32_t)((ks * 16 + a_lkoff) * 2);
                ldm_x4(af[mt], addr);
            }
            #pragma unroll
            for (int nt2 = 0; nt2 < 2; nt2++) {
                uint32_t addr = Bs + (uint32_t)((wn_ * 32 + nt2 * 16 + b_lrow) * PITCH)
                              + (uint32_t)((ks * 16 + b_lkoff) * 2);
                ldm_x4(bf[nt2], addr);
            }
            #pragma unroll
            for (int mt = 0; mt < 4; mt++)
                #pragma unroll
                for (int nt = 0; nt < 4; nt++)
                    mma16816(acc[mt][nt], af[mt], bf[nt >> 1][(nt & 1) * 2], bf[nt >> 1][(nt & 1) * 2 + 1]);
        }

        // ---- stage chunk i+1 B ----
        if (more) {
            sts128(Bsn + brow_off +  0, dec8(w0.x, w0.y, w0.z, aa, nb));
            sts128(Bsn + brow_off + 16, dec8(w0.w, w1.x, w1.y, aa, nb));
            sts128(Bsn + brow_off + 32, dec8(w1.z, w1.w, w2.x, aa, nb));
            sts128(Bsn + brow_off + 48, dec8(w2.y, w2.z, w2.w, aa, nb));
            asm volatile("cp.async.wait_group 0;" ::: "memory");
        }
        __syncthreads();
    }

    // ---- epilogue ----
    #pragma unroll
    for (int mt = 0; mt < 4; mt++) {
        #pragma unroll
        for (int nt = 0; nt < 4; nt++) {
            int m = m0 + wm * 64 + mt * 16 + (lid >> 2);
            int nl = wn_ * 32 + nt * 8 + (lid & 3) * 2;
            float2 v0, v1;
            v0.x = acc[mt][nt][0] + bias_s[nl];
            v0.y = acc[mt][nt][1] + bias_s[nl + 1];
            v1.x = acc[mt][nt][2] + bias_s[nl];
            v1.y = acc[mt][nt][3] + bias_s[nl + 1];
            *(float2*)(out + (size_t)m * OUTF + n0 + nl) = v0;
            *(float2*)(out + (size_t)(m + 8) * OUTF + n0 + nl) = v1;
        }
    }
}

// ---------------- launch ----------------
extern "C" void kernel_launch(void* const* d_in, const int* in_sizes, int n_in,
                              void* d_out, int out_size) {
    // Bind inputs by element count (robust to metadata ordering).
    // All four counts are distinct: x=2097152, wq=16908288, wn=1409024, bias=11008.
    const float* x    = 0;
    const int*   wq   = 0;
    const void*  wn   = 0;
    const float* bias = 0;
    for (int i = 0; i < n_in; i++) {
        switch (in_sizes[i]) {
            case N_X:  x    = (const float*)d_in[i]; break;
            case N_WQ: wq   = (const int*)d_in[i];   break;
            case N_WN: wn   = d_in[i];               break;
            case N_B:  bias = (const float*)d_in[i]; break;
            default: break;
        }
    }
    if (!x)    x    = (const float*)d_in[0];
    if (!wq)   wq   = (const int*)d_in[1];
    if (!wn)   wn   = d_in[2];
    if (!bias) bias = (const float*)d_in[3];

    float* out = (float*)d_out;

    cudaFuncSetAttribute(l3b_gemm, cudaFuncAttributeMaxDynamicSharedMemorySize, SMEM_BYTES);

    // Normalize weight_norm dtype (f32/f16/bf16 auto-detect) into g_wn (fp16).
    detect_wn_kernel<<<1, 1>>>(wn);
    convert_wn_kernel<<<(NUM_GROUPS + 511) / 512, 512>>>(wn);

    // x: fp32 -> fp16
    convert_x_kernel<<<(MTOT * INF / 2) / 512, 512>>>(x);

    dim3 grid(MTOT / M_TILE, OUTF / N_TILE);  // (4, 86), m fast-varying
    l3b_gemm<<<grid, NTHREADS, SMEM_BYTES>>>(wq, bias, out);
}

// round 9
// speedup vs baseline: 1.2692x; 1.2692x over previous
#include <cuda_runtime.h>
#include <cuda_fp16.h>
#include <cuda_bf16.h>
#include <stdint.h>

// Problem constants
#define OUTF   11008
#define INF    4096
#define MTOT   512
#define NUM_GROUPS 1409024               // OUTF*INF/32

#define N_TILE 128
#define M_TILE 128
#define KCHUNK 64
#define KSPLIT 4
#define NCHUNK_JOB (INF / KCHUNK / KSPLIT)   // 16 chunks per job
#define NTHREADS 256

#define PITCH 144                        // 128B data + 16B pad per row (conflict-free ldmatrix)
#define STAGE_BYTES (128 * PITCH)        // 18432 per tile (A or B)
#define SMEM_BYTES (1024 + 4 * STAGE_BYTES)  // header + 2 stages x (A+B) = 74752

// element counts for input identification (all distinct)
#define N_X   (MTOT * INF)               // 2,097,152 fp32
#define N_WQ  (NUM_GROUPS * 12)          // 16,908,288 int32
#define N_WN  NUM_GROUPS                 // 1,409,024 (dtype auto-detected)
#define N_B   OUTF                       // 11,008 fp32

__device__ __align__(16) __half g_xh[MTOT * INF];   // fp16-converted activations (4 MB)
__device__ __align__(16) __half g_wn[NUM_GROUPS];   // normalized norms (2.8 MB)
__device__ int g_wn_mode;

// ---------------- helpers ----------------
__device__ __forceinline__ uint32_t smem_u32(const void* p) {
    uint32_t a;
    asm("{ .reg .u64 t; cvta.to.shared.u64 t, %1; cvt.u32.u64 %0, t; }" : "=r"(a) : "l"(p));
    return a;
}

__device__ __forceinline__ void sts128(uint32_t addr, uint4 v) {
    asm volatile("st.shared.v4.b32 [%0], {%1,%2,%3,%4};"
                 :: "r"(addr), "r"(v.x), "r"(v.y), "r"(v.z), "r"(v.w) : "memory");
}

__device__ __forceinline__ void cpasync16(uint32_t dst, const void* src) {
    asm volatile("cp.async.cg.shared.global [%0], [%1], 16;" :: "r"(dst), "l"(src) : "memory");
}

__device__ __forceinline__ void ldm_x4(uint32_t* r, uint32_t addr) {
    asm volatile("ldmatrix.sync.aligned.m8n8.x4.shared.b16 {%0,%1,%2,%3}, [%4];"
                 : "=r"(r[0]), "=r"(r[1]), "=r"(r[2]), "=r"(r[3]) : "r"(addr));
}

__device__ __forceinline__ void mma16816(float* c, const uint32_t* a, const uint32_t b0, const uint32_t b1) {
    asm volatile(
        "mma.sync.aligned.m16n8k16.row.col.f32.f16.f16.f32 "
        "{%0,%1,%2,%3}, {%4,%5,%6,%7}, {%8,%9}, {%0,%1,%2,%3};"
        : "+f"(c[0]), "+f"(c[1]), "+f"(c[2]), "+f"(c[3])
        : "r"(a[0]), "r"(a[1]), "r"(a[2]), "r"(a[3]), "r"(b0), "r"(b1));
}

// Decode 8 3-bit codes from 3 bytes (each held in an int32), dequantize, pack to 4x half2.
__device__ __forceinline__ uint4 dec8(int b0, int b1, int b2, float a, float nb) {
    float w0 = fmaf((float)(b0 & 7), a, nb);
    float w1 = fmaf((float)((b0 >> 3) & 7), a, nb);
    float w2 = fmaf((float)(((b0 >> 6) & 3) | ((b1 & 1) << 2)), a, nb);
    float w3 = fmaf((float)((b1 >> 1) & 7), a, nb);
    float w4 = fmaf((float)((b1 >> 4) & 7), a, nb);
    float w5 = fmaf((float)(((b1 >> 7) & 1) | ((b2 & 3) << 1)), a, nb);
    float w6 = fmaf((float)((b2 >> 2) & 7), a, nb);
    float w7 = fmaf((float)((b2 >> 5) & 7), a, nb);
    uint4 u;
    asm("cvt.rn.f16x2.f32 %0, %1, %2;" : "=r"(u.x) : "f"(w1), "f"(w0));
    asm("cvt.rn.f16x2.f32 %0, %1, %2;" : "=r"(u.y) : "f"(w3), "f"(w2));
    asm("cvt.rn.f16x2.f32 %0, %1, %2;" : "=r"(u.z) : "f"(w5), "f"(w4));
    asm("cvt.rn.f16x2.f32 %0, %1, %2;" : "=r"(u.w) : "f"(w7), "f"(w6));
    return u;
}

// ---------------- weight_norm dtype detection + normalization ----------------
// Norms lie in (0.01, 0.11). 256 threads each vote on one element under three
// interpretations; the interpretation with most in-range values wins.
__global__ void detect_wn_kernel(const void* __restrict__ wn) {
    __shared__ int votes[3];
    if (threadIdx.x < 3) votes[threadIdx.x] = 0;
    __syncthreads();
    int i = threadIdx.x;
    float a = ((const float*)wn)[i];
    float b = __half2float(((const __half*)wn)[i]);
    float c = __bfloat162float(((const __nv_bfloat16*)wn)[i]);
    if (a > 0.009f && a < 0.115f) atomicAdd(&votes[0], 1);
    if (b > 0.009f && b < 0.115f) atomicAdd(&votes[1], 1);
    if (c > 0.009f && c < 0.115f) atomicAdd(&votes[2], 1);
    __syncthreads();
    if (threadIdx.x == 0) {
        int mode = 1, best = votes[1];
        if (votes[0] > best) { best = votes[0]; mode = 0; }
        if (votes[2] > best) { best = votes[2]; mode = 2; }
        g_wn_mode = mode;
    }
}

__global__ void __launch_bounds__(512) convert_wn_kernel(const void* __restrict__ wn) {
    int i = blockIdx.x * blockDim.x + threadIdx.x;
    if (i >= NUM_GROUPS) return;
    int mode = g_wn_mode;
    float v;
    if (mode == 0)      v = ((const float*)wn)[i];
    else if (mode == 1) v = __half2float(((const __half*)wn)[i]);
    else                v = __bfloat162float(((const __nv_bfloat16*)wn)[i]);
    g_wn[i] = __float2half_rn(v);
}

// ---------------- x fp32 -> fp16 conversion ----------------
__global__ void __launch_bounds__(512) convert_x_kernel(const float* __restrict__ x) {
    int i = blockIdx.x * blockDim.x + threadIdx.x;   // one half2 per thread
    float2 v = ((const float2*)x)[i];
    ((__half2*)g_xh)[i] = __floats2half2_rn(v.x, v.y);
}

// ---------------- out init: broadcast bias (out is poisoned by harness) ----------------
__global__ void __launch_bounds__(256) init_out_kernel(const float* __restrict__ bias,
                                                       float* __restrict__ out) {
    int i = blockIdx.x * blockDim.x + threadIdx.x;     // float4 index
    int n4 = (i % (OUTF / 4)) * 4;
    float4 b = *(const float4*)(bias + n4);
    ((float4*)out)[i] = b;
}

// ---------------- fused dequant + GEMM, split-K (HMMA; tcgen05 not available on sm_103 base) ----
__global__ void __launch_bounds__(NTHREADS) l3b_gemm(
    const int* __restrict__ wq, float* __restrict__ out)
{
    extern __shared__ char smem[];
    const uint32_t sb = smem_u32(smem);
    const int tid = threadIdx.x;
    const int wid = tid >> 5, lid = tid & 31;
    const int wm = wid >> 2, wn_ = wid & 3;          // 2x4 warp grid
    const int m0 = blockIdx.x * M_TILE;              // m fast-varying: L2 weight reuse
    const int n0 = blockIdx.y * N_TILE;
    const int c0 = blockIdx.z * NCHUNK_JOB;          // split-K chunk base

    const uint32_t As0 = sb + 1024;
    const uint32_t Bs0 = As0 + 2 * STAGE_BYTES;

    // dequant task: thread -> (row r in 0..127, half-chunk sub in 0..1); one 32-group each
    const int r = tid >> 1, sub = tid & 1;
    const long grow = (long)(n0 + r) * (INF / 32);
    const uint32_t brow_off = (uint32_t)(r * PITCH + sub * 64);

    // ldmatrix lane addressing
    const uint32_t a_lrow = (uint32_t)(lid & 15);
    const uint32_t a_lkoff = (uint32_t)((lid >> 4) * 8);
    const uint32_t b_lrow = (uint32_t)(((lid >> 4) << 3) + (lid & 7));
    const uint32_t b_lkoff = (uint32_t)(((lid >> 3) & 1) * 8);

    float acc[4][4][4];
    #pragma unroll
    for (int mt = 0; mt < 4; mt++)
        #pragma unroll
        for (int nt = 0; nt < 4; nt++)
            #pragma unroll
            for (int e = 0; e < 4; e++) acc[mt][nt][e] = 0.0f;

    // ---- prologue: stage chunk c0 into buffer 0 ----
    {
        #pragma unroll
        for (int p = 0; p < 4; p++) {
            int idx = p * NTHREADS + tid;                 // 0..1023
            int row = idx >> 3, col = idx & 7;
            cpasync16(As0 + (uint32_t)(row * PITCH + col * 16),
                      g_xh + (size_t)(m0 + row) * INF + c0 * KCHUNK + col * 8);
        }
        asm volatile("cp.async.commit_group;" ::: "memory");
        const long g = grow + c0 * 2 + sub;
        const int4* pk = (const int4*)wq + g * 3;
        int4 w0 = __ldg(pk), w1 = __ldg(pk + 1), w2 = __ldg(pk + 2);
        float norm = __half2float(g_wn[g]);
        float aa = norm * (2.0f / 7.0f), nb = -norm;
        sts128(Bs0 + brow_off +  0, dec8(w0.x, w0.y, w0.z, aa, nb));
        sts128(Bs0 + brow_off + 16, dec8(w0.w, w1.x, w1.y, aa, nb));
        sts128(Bs0 + brow_off + 32, dec8(w1.z, w1.w, w2.x, aa, nb));
        sts128(Bs0 + brow_off + 48, dec8(w2.y, w2.z, w2.w, aa, nb));
        asm volatile("cp.async.wait_group 0;" ::: "memory");
        __syncthreads();
    }

    #pragma unroll 1
    for (int i = 0; i < NCHUNK_JOB; i++) {
        const int s = i & 1;
        const uint32_t As = As0 + s * STAGE_BYTES;
        const uint32_t Bs = Bs0 + s * STAGE_BYTES;
        const uint32_t Asn = As0 + (s ^ 1) * STAGE_BYTES;
        const uint32_t Bsn = Bs0 + (s ^ 1) * STAGE_BYTES;

        int4 w0, w1, w2; float aa = 0.f, nb = 0.f;
        const bool more = (i + 1 < NCHUNK_JOB);
        if (more) {
            const int ci = c0 + i + 1;
            #pragma unroll
            for (int p = 0; p < 4; p++) {
                int idx = p * NTHREADS + tid;
                int row = idx >> 3, col = idx & 7;
                cpasync16(Asn + (uint32_t)(row * PITCH + col * 16),
                          g_xh + (size_t)(m0 + row) * INF + ci * KCHUNK + col * 8);
            }
            asm volatile("cp.async.commit_group;" ::: "memory");
            const long g = grow + ci * 2 + sub;
            const int4* pk = (const int4*)wq + g * 3;
            w0 = __ldg(pk); w1 = __ldg(pk + 1); w2 = __ldg(pk + 2);
            float norm = __half2float(g_wn[g]);
            aa = norm * (2.0f / 7.0f); nb = -norm;
        }

        // ---- compute chunk i: 4 k16 steps ----
        #pragma unroll
        for (int ks = 0; ks < 4; ks++) {
            uint32_t af[4][4], bf[2][4];
            #pragma unroll
            for (int mt = 0; mt < 4; mt++) {
                uint32_t addr = As + (uint32_t)((wm * 64 + mt * 16 + a_lrow) * PITCH)
                              + (uint32_t)((ks * 16 + a_lkoff) * 2);
                ldm_x4(af[mt], addr);
            }
            #pragma unroll
            for (int nt2 = 0; nt2 < 2; nt2++) {
                uint32_t addr = Bs + (uint32_t)((wn_ * 32 + nt2 * 16 + b_lrow) * PITCH)
                              + (uint32_t)((ks * 16 + b_lkoff) * 2);
                ldm_x4(bf[nt2], addr);
            }
            #pragma unroll
            for (int mt = 0; mt < 4; mt++)
                #pragma unroll
                for (int nt = 0; nt < 4; nt++)
                    mma16816(acc[mt][nt], af[mt], bf[nt >> 1][(nt & 1) * 2], bf[nt >> 1][(nt & 1) * 2 + 1]);
        }

        // ---- stage chunk i+1 B ----
        if (more) {
            sts128(Bsn + brow_off +  0, dec8(w0.x, w0.y, w0.z, aa, nb));
            sts128(Bsn + brow_off + 16, dec8(w0.w, w1.x, w1.y, aa, nb));
            sts128(Bsn + brow_off + 32, dec8(w1.z, w1.w, w2.x, aa, nb));
            sts128(Bsn + brow_off + 48, dec8(w2.y, w2.z, w2.w, aa, nb));
            asm volatile("cp.async.wait_group 0;" ::: "memory");
        }
        __syncthreads();
    }

    // ---- epilogue: atomic accumulate split-K partials (bias pre-broadcast by init) ----
    #pragma unroll
    for (int mt = 0; mt < 4; mt++) {
        #pragma unroll
        for (int nt = 0; nt < 4; nt++) {
            int m = m0 + wm * 64 + mt * 16 + (lid >> 2);
            int nl = n0 + wn_ * 32 + nt * 8 + (lid & 3) * 2;
            float* p0 = out + (size_t)m * OUTF + nl;
            float* p1 = out + (size_t)(m + 8) * OUTF + nl;
            atomicAdd(p0,     acc[mt][nt][0]);
            atomicAdd(p0 + 1, acc[mt][nt][1]);
            atomicAdd(p1,     acc[mt][nt][2]);
            atomicAdd(p1 + 1, acc[mt][nt][3]);
        }
    }
}

// ---------------- launch ----------------
extern "C" void kernel_launch(void* const* d_in, const int* in_sizes, int n_in,
                              void* d_out, int out_size) {
    // Bind inputs by element count (robust to metadata ordering).
    const float* x    = 0;
    const int*   wq   = 0;
    const void*  wn   = 0;
    const float* bias = 0;
    for (int i = 0; i < n_in; i++) {
        switch (in_sizes[i]) {
            case N_X:  x    = (const float*)d_in[i]; break;
            case N_WQ: wq   = (const int*)d_in[i];   break;
            case N_WN: wn   = d_in[i];               break;
            case N_B:  bias = (const float*)d_in[i]; break;
            default: break;
        }
    }
    if (!x)    x    = (const float*)d_in[0];
    if (!wq)   wq   = (const int*)d_in[1];
    if (!wn)   wn   = d_in[2];
    if (!bias) bias = (const float*)d_in[3];

    float* out = (float*)d_out;

    cudaFuncSetAttribute(l3b_gemm, cudaFuncAttributeMaxDynamicSharedMemorySize, SMEM_BYTES);

    // Normalize weight_norm dtype (f32/f16/bf16 auto-detect) into g_wn (fp16).
    detect_wn_kernel<<<1, 256>>>(wn);
    convert_wn_kernel<<<(NUM_GROUPS + 511) / 512, 512>>>(wn);

    // x: fp32 -> fp16
    convert_x_kernel<<<(MTOT * INF / 2) / 512, 512>>>(x);

    // out = bias (broadcast); split-K jobs accumulate on top
    init_out_kernel<<<(MTOT * OUTF / 4) / 256, 256>>>(bias, out);

    dim3 grid(MTOT / M_TILE, OUTF / N_TILE, KSPLIT);  // (4, 86, 4)
    l3b_gemm<<<grid, NTHREADS, SMEM_BYTES>>>(wq, out);
}

// round 10
// speedup vs baseline: 1.3091x; 1.0315x over previous
#include <cuda_runtime.h>
#include <cuda_fp16.h>
#include <cuda_bf16.h>
#include <stdint.h>

// Problem constants
#define OUTF   11008
#define INF    4096
#define MTOT   512
#define NUM_GROUPS 1409024               // OUTF*INF/32

#define N_TILE 128
#define M_TILE 128
#define KCHUNK 64
#define KSPLIT 4
#define NCHUNK_JOB (INF / KCHUNK / KSPLIT)   // 16 chunks per job
#define NTHREADS 256

#define PITCH 144                        // 128B data + 16B pad per row (conflict-free ldmatrix)
#define STAGE_BYTES (128 * PITCH)        // 18432 per tile (A or B)
// A: 3 stages, B: 2 stages
#define SMEM_BYTES (1024 + 5 * STAGE_BYTES)  // 93184

// element counts for input identification (all distinct)
#define N_X   (MTOT * INF)               // 2,097,152 fp32
#define N_WQ  (NUM_GROUPS * 12)          // 16,908,288 int32
#define N_WN  NUM_GROUPS                 // 1,409,024 (dtype auto-detected)
#define N_B   OUTF                       // 11,008 fp32

// prep kernel block partition (512 threads each)
#define NB_WN  (NUM_GROUPS / 512)        // 2752
#define NB_X   (MTOT * INF / 2 / 512)    // 2048
#define NB_OUT (MTOT * OUTF / 4 / 512)   // 2752

__device__ __align__(16) __half g_xh[MTOT * INF];   // fp16-converted activations (4 MB)
__device__ __align__(16) __half g_wn[NUM_GROUPS];   // normalized norms (2.8 MB)
__device__ int g_wn_mode;

// ---------------- helpers ----------------
__device__ __forceinline__ uint32_t smem_u32(const void* p) {
    uint32_t a;
    asm("{ .reg .u64 t; cvta.to.shared.u64 t, %1; cvt.u32.u64 %0, t; }" : "=r"(a) : "l"(p));
    return a;
}

__device__ __forceinline__ void sts128(uint32_t addr, uint4 v) {
    asm volatile("st.shared.v4.b32 [%0], {%1,%2,%3,%4};"
                 :: "r"(addr), "r"(v.x), "r"(v.y), "r"(v.z), "r"(v.w) : "memory");
}

__device__ __forceinline__ void cpasync16(uint32_t dst, const void* src) {
    asm volatile("cp.async.cg.shared.global [%0], [%1], 16;" :: "r"(dst), "l"(src) : "memory");
}

__device__ __forceinline__ void ldm_x4(uint32_t* r, uint32_t addr) {
    asm volatile("ldmatrix.sync.aligned.m8n8.x4.shared.b16 {%0,%1,%2,%3}, [%4];"
                 : "=r"(r[0]), "=r"(r[1]), "=r"(r[2]), "=r"(r[3]) : "r"(addr));
}

__device__ __forceinline__ void mma16816(float* c, const uint32_t* a, const uint32_t b0, const uint32_t b1) {
    asm volatile(
        "mma.sync.aligned.m16n8k16.row.col.f32.f16.f16.f32 "
        "{%0,%1,%2,%3}, {%4,%5,%6,%7}, {%8,%9}, {%0,%1,%2,%3};"
        : "+f"(c[0]), "+f"(c[1]), "+f"(c[2]), "+f"(c[3])
        : "r"(a[0]), "r"(a[1]), "r"(a[2]), "r"(a[3]), "r"(b0), "r"(b1));
}

// Decode 8 3-bit codes from 3 bytes (each held in an int32), dequantize, pack to 4x half2.
__device__ __forceinline__ uint4 dec8(int b0, int b1, int b2, float a, float nb) {
    float w0 = fmaf((float)(b0 & 7), a, nb);
    float w1 = fmaf((float)((b0 >> 3) & 7), a, nb);
    float w2 = fmaf((float)(((b0 >> 6) & 3) | ((b1 & 1) << 2)), a, nb);
    float w3 = fmaf((float)((b1 >> 1) & 7), a, nb);
    float w4 = fmaf((float)((b1 >> 4) & 7), a, nb);
    float w5 = fmaf((float)(((b1 >> 7) & 1) | ((b2 & 3) << 1)), a, nb);
    float w6 = fmaf((float)((b2 >> 2) & 7), a, nb);
    float w7 = fmaf((float)((b2 >> 5) & 7), a, nb);
    uint4 u;
    asm("cvt.rn.f16x2.f32 %0, %1, %2;" : "=r"(u.x) : "f"(w1), "f"(w0));
    asm("cvt.rn.f16x2.f32 %0, %1, %2;" : "=r"(u.y) : "f"(w3), "f"(w2));
    asm("cvt.rn.f16x2.f32 %0, %1, %2;" : "=r"(u.z) : "f"(w5), "f"(w4));
    asm("cvt.rn.f16x2.f32 %0, %1, %2;" : "=r"(u.w) : "f"(w7), "f"(w6));
    return u;
}

// ---------------- weight_norm dtype detection ----------------
// Norms lie in (0.01, 0.11). 256 threads vote under three interpretations.
__global__ void detect_wn_kernel(const void* __restrict__ wn) {
    __shared__ int votes[3];
    if (threadIdx.x < 3) votes[threadIdx.x] = 0;
    __syncthreads();
    int i = threadIdx.x;
    float a = ((const float*)wn)[i];
    float b = __half2float(((const __half*)wn)[i]);
    float c = __bfloat162float(((const __nv_bfloat16*)wn)[i]);
    if (a > 0.009f && a < 0.115f) atomicAdd(&votes[0], 1);
    if (b > 0.009f && b < 0.115f) atomicAdd(&votes[1], 1);
    if (c > 0.009f && c < 0.115f) atomicAdd(&votes[2], 1);
    __syncthreads();
    if (threadIdx.x == 0) {
        int mode = 1, best = votes[1];
        if (votes[0] > best) { best = votes[0]; mode = 0; }
        if (votes[2] > best) { best = votes[2]; mode = 2; }
        g_wn_mode = mode;
    }
}

// ---------------- fused prep: wn convert + x convert + out init ----------------
__global__ void __launch_bounds__(512) prep_kernel(
    const void* __restrict__ wn, const float* __restrict__ x,
    const float* __restrict__ bias, float* __restrict__ out)
{
    int b = blockIdx.x;
    if (b < NB_WN) {
        int i = b * 512 + threadIdx.x;
        int mode = g_wn_mode;
        float v;
        if (mode == 0)      v = ((const float*)wn)[i];
        else if (mode == 1) v = __half2float(((const __half*)wn)[i]);
        else                v = __bfloat162float(((const __nv_bfloat16*)wn)[i]);
        g_wn[i] = __float2half_rn(v);
    } else if (b < NB_WN + NB_X) {
        int i = (b - NB_WN) * 512 + threadIdx.x;
        float2 v = ((const float2*)x)[i];
        ((__half2*)g_xh)[i] = __floats2half2_rn(v.x, v.y);
    } else {
        int i = (b - NB_WN - NB_X) * 512 + threadIdx.x;     // float4 index
        int n4 = (i % (OUTF / 4)) * 4;
        float4 bb = *(const float4*)(bias + n4);
        ((float4*)out)[i] = bb;
    }
}

// ---------------- fused dequant + GEMM, split-K, 3-stage A pipeline ----------------
__global__ void __launch_bounds__(NTHREADS) l3b_gemm(
    const int* __restrict__ wq, float* __restrict__ out)
{
    extern __shared__ char smem[];
    const uint32_t sb = smem_u32(smem);
    const int tid = threadIdx.x;
    const int wid = tid >> 5, lid = tid & 31;
    const int wm = wid >> 2, wn_ = wid & 3;          // 2x4 warp grid
    const int m0 = blockIdx.x * M_TILE;              // m fast-varying: L2 weight reuse
    const int n0 = blockIdx.y * N_TILE;
    const int c0 = blockIdx.z * NCHUNK_JOB;          // split-K chunk base

    const uint32_t As0 = sb + 1024;                  // 3 A stages
    const uint32_t Bb  = As0 + 3 * STAGE_BYTES;      // 2 B stages

    // dequant task: thread -> (row r in 0..127, half-chunk sub in 0..1); one 32-group each
    const int r = tid >> 1, sub = tid & 1;
    const long grow = (long)(n0 + r) * (INF / 32);
    const uint32_t brow_off = (uint32_t)(r * PITCH + sub * 64);

    // ldmatrix lane addressing
    const uint32_t a_lrow = (uint32_t)(lid & 15);
    const uint32_t a_lkoff = (uint32_t)((lid >> 4) * 8);
    const uint32_t b_lrow = (uint32_t)(((lid >> 4) << 3) + (lid & 7));
    const uint32_t b_lkoff = (uint32_t)(((lid >> 3) & 1) * 8);

    float acc[4][4][4];
    #pragma unroll
    for (int mt = 0; mt < 4; mt++)
        #pragma unroll
        for (int nt = 0; nt < 4; nt++)
            #pragma unroll
            for (int e = 0; e < 4; e++) acc[mt][nt][e] = 0.0f;

    // ---- prologue: stage A(c0)->A0, A(c0+1)->A1, B(c0)->B0 ----
    {
        #pragma unroll
        for (int p = 0; p < 4; p++) {
            int idx = p * NTHREADS + tid;                 // 0..1023
            int row = idx >> 3, col = idx & 7;
            cpasync16(As0 + (uint32_t)(row * PITCH + col * 16),
                      g_xh + (size_t)(m0 + row) * INF + c0 * KCHUNK + col * 8);
        }
        asm volatile("cp.async.commit_group;" ::: "memory");
        #pragma unroll
        for (int p = 0; p < 4; p++) {
            int idx = p * NTHREADS + tid;
            int row = idx >> 3, col = idx & 7;
            cpasync16(As0 + STAGE_BYTES + (uint32_t)(row * PITCH + col * 16),
                      g_xh + (size_t)(m0 + row) * INF + (c0 + 1) * KCHUNK + col * 8);
        }
        asm volatile("cp.async.commit_group;" ::: "memory");

        const long g = grow + c0 * 2 + sub;
        const int4* pk = (const int4*)wq + g * 3;
        int4 w0 = __ldg(pk), w1 = __ldg(pk + 1), w2 = __ldg(pk + 2);
        float norm = __half2float(g_wn[g]);
        float aa = norm * (2.0f / 7.0f), nb = -norm;
        sts128(Bb + brow_off +  0, dec8(w0.x, w0.y, w0.z, aa, nb));
        sts128(Bb + brow_off + 16, dec8(w0.w, w1.x, w1.y, aa, nb));
        sts128(Bb + brow_off + 32, dec8(w1.z, w1.w, w2.x, aa, nb));
        sts128(Bb + brow_off + 48, dec8(w2.y, w2.z, w2.w, aa, nb));
        asm volatile("cp.async.wait_group 1;" ::: "memory");   // A(c0) landed
        __syncthreads();
    }

    int rd3 = 0;                                     // A read stage (i % 3)

    #pragma unroll 1
    for (int i = 0; i < NCHUNK_JOB; i++) {
        const uint32_t As = As0 + (uint32_t)rd3 * STAGE_BYTES;
        const uint32_t Bs = Bb + (uint32_t)(i & 1) * STAGE_BYTES;

        // ---- prefetch B(i+1) packed words into registers ----
        int4 w0, w1, w2; float aa = 0.f, nb = 0.f;
        const bool more = (i + 1 < NCHUNK_JOB);
        const bool more2 = (i + 2 < NCHUNK_JOB);
        if (more) {
            const int ci = c0 + i + 1;
            const long g = grow + ci * 2 + sub;
            const int4* pk = (const int4*)wq + g * 3;
            w0 = __ldg(pk); w1 = __ldg(pk + 1); w2 = __ldg(pk + 2);
            float norm = __half2float(g_wn[g]);
            aa = norm * (2.0f / 7.0f); nb = -norm;
        }
        // ---- issue A(i+2) cp.async into stage (rd3+2)%3 ----
        if (more2) {
            int wr3 = rd3 + 2; if (wr3 >= 3) wr3 -= 3;
            const uint32_t Aw = As0 + (uint32_t)wr3 * STAGE_BYTES;
            const int ci = c0 + i + 2;
            #pragma unroll
            for (int p = 0; p < 4; p++) {
                int idx = p * NTHREADS + tid;
                int row = idx >> 3, col = idx & 7;
                cpasync16(Aw + (uint32_t)(row * PITCH + col * 16),
                          g_xh + (size_t)(m0 + row) * INF + ci * KCHUNK + col * 8);
            }
            asm volatile("cp.async.commit_group;" ::: "memory");
        }

        // ---- compute chunk i: 4 k16 steps ----
        #pragma unroll
        for (int ks = 0; ks < 4; ks++) {
            uint32_t af[4][4], bf[2][4];
            #pragma unroll
            for (int mt = 0; mt < 4; mt++) {
                uint32_t addr = As + (uint32_t)((wm * 64 + mt * 16 + a_lrow) * PITCH)
                              + (uint32_t)((ks * 16 + a_lkoff) * 2);
                ldm_x4(af[mt], addr);
            }
            #pragma unroll
            for (int nt2 = 0; nt2 < 2; nt2++) {
                uint32_t addr = Bs + (uint32_t)((wn_ * 32 + nt2 * 16 + b_lrow) * PITCH)
                              + (uint32_t)((ks * 16 + b_lkoff) * 2);
                ldm_x4(bf[nt2], addr);
            }
            #pragma unroll
            for (int mt = 0; mt < 4; mt++)
                #pragma unroll
                for (int nt = 0; nt < 4; nt++)
                    mma16816(acc[mt][nt], af[mt], bf[nt >> 1][(nt & 1) * 2], bf[nt >> 1][(nt & 1) * 2 + 1]);
        }

        // ---- stage B(i+1); then ensure A(i+1) landed; sync ----
        if (more) {
            const uint32_t Bw = Bb + (uint32_t)((i + 1) & 1) * STAGE_BYTES;
            sts128(Bw + brow_off +  0, dec8(w0.x, w0.y, w0.z, aa, nb));
            sts128(Bw + brow_off + 16, dec8(w0.w, w1.x, w1.y, aa, nb));
            sts128(Bw + brow_off + 32, dec8(w1.z, w1.w, w2.x, aa, nb));
            sts128(Bw + brow_off + 48, dec8(w2.y, w2.z, w2.w, aa, nb));
            if (more2) { asm volatile("cp.async.wait_group 1;" ::: "memory"); }
            else       { asm volatile("cp.async.wait_group 0;" ::: "memory"); }
            __syncthreads();
        }

        rd3++; if (rd3 == 3) rd3 = 0;
    }

    // ---- epilogue: atomic accumulate split-K partials (bias pre-broadcast by prep) ----
    #pragma unroll
    for (int mt = 0; mt < 4; mt++) {
        #pragma unroll
        for (int nt = 0; nt < 4; nt++) {
            int m = m0 + wm * 64 + mt * 16 + (lid >> 2);
            int nl = n0 + wn_ * 32 + nt * 8 + (lid & 3) * 2;
            float* p0 = out + (size_t)m * OUTF + nl;
            float* p1 = out + (size_t)(m + 8) * OUTF + nl;
            atomicAdd(p0,     acc[mt][nt][0]);
            atomicAdd(p0 + 1, acc[mt][nt][1]);
            atomicAdd(p1,     acc[mt][nt][2]);
            atomicAdd(p1 + 1, acc[mt][nt][3]);
        }
    }
}

// ---------------- launch ----------------
extern "C" void kernel_launch(void* const* d_in, const int* in_sizes, int n_in,
                              void* d_out, int out_size) {
    // Bind inputs by element count (robust to metadata ordering).
    const float* x    = 0;
    const int*   wq   = 0;
    const void*  wn   = 0;
    const float* bias = 0;
    for (int i = 0; i < n_in; i++) {
        switch (in_sizes[i]) {
            case N_X:  x    = (const float*)d_in[i]; break;
            case N_WQ: wq   = (const int*)d_in[i];   break;
            case N_WN: wn   = d_in[i];               break;
            case N_B:  bias = (const float*)d_in[i]; break;
            default: break;
        }
    }
    if (!x)    x    = (const float*)d_in[0];
    if (!wq)   wq   = (const int*)d_in[1];
    if (!wn)   wn   = d_in[2];
    if (!bias) bias = (const float*)d_in[3];

    float* out = (float*)d_out;

    cudaFuncSetAttribute(l3b_gemm, cudaFuncAttributeMaxDynamicSharedMemorySize, SMEM_BYTES);

    detect_wn_kernel<<<1, 256>>>(wn);
    prep_kernel<<<NB_WN + NB_X + NB_OUT, 512>>>(wn, x, bias, out);

    dim3 grid(MTOT / M_TILE, OUTF / N_TILE, KSPLIT);  // (4, 86, 4)
    l3b_gemm<<<grid, NTHREADS, SMEM_BYTES>>>(wq, out);
}